// round 5
// baseline (speedup 1.0000x reference)
#include <cuda_runtime.h>
#include <cstdint>

#define NODES_MAX 100000
#define HDIM 256
#define FIN 128

// Scratch (allocation-free rule: __device__ globals)
__device__ __align__(16) float g_h[(size_t)NODES_MAX * HDIM];
__device__ __align__(16) float g_m[(size_t)NODES_MAX * HDIM];
__device__ __align__(16) float g_acc[(size_t)NODES_MAX * HDIM];
__device__ float g_dinv[NODES_MAX];

// ---------------- degree / norm ----------------
__global__ void init_deg_kernel(float* deg, int n) {
    int i = blockIdx.x * blockDim.x + threadIdx.x;
    if (i < n) deg[i] = 1.0f;  // self-loop
}

__global__ void count_deg_kernel(const int* __restrict__ dst, float* deg, int E) {
    int i = blockIdx.x * blockDim.x + threadIdx.x;
    if (i < E) atomicAdd(&deg[dst[i]], 1.0f);
}

__global__ void dinv_kernel(float* deg, int n) {
    int i = blockIdx.x * blockDim.x + threadIdx.x;
    if (i < n) deg[i] = rsqrtf(deg[i]);  // deg >= 1 always
}

// ---------------- SGEMM: C[M,Ncols] = A[M,K] @ B[K,Ncols] (+bias)(+relu) ----------------
// Block tile 128x128, BK=8, 256 threads, 8x8 per-thread microtile.
#define BM 128
#define BN 128
#define BK 8

__global__ __launch_bounds__(256, 2)
void sgemm_kernel(const float* __restrict__ A, const float* __restrict__ B,
                  const float* __restrict__ bias, float* __restrict__ C,
                  int M, int Ncols, int K, int relu)
{
    __shared__ float As[BK][BM];
    __shared__ float Bs[BK][BN];

    int tid = threadIdx.x;
    int block_row = blockIdx.x * BM;
    int block_col = blockIdx.y * BN;

    // A-tile load map: 128x8 floats = 256 float4; thread t -> row t/2, col (t&1)*4
    int a_row = tid >> 1;
    int a_col = (tid & 1) * 4;
    // B-tile load map: 8x128 floats = 256 float4; thread t -> row t/32, col (t&31)*4
    int b_row = tid >> 5;
    int b_col = (tid & 31) * 4;

    int tm = (tid >> 4) * 8;   // 0..120
    int tn = (tid & 15) * 8;   // 0..120

    float acc[8][8];
    #pragma unroll
    for (int i = 0; i < 8; i++)
        #pragma unroll
        for (int j = 0; j < 8; j++) acc[i][j] = 0.0f;

    for (int k0 = 0; k0 < K; k0 += BK) {
        int gr = block_row + a_row;
        float4 av = make_float4(0.f, 0.f, 0.f, 0.f);
        if (gr < M) av = *(const float4*)(A + (size_t)gr * K + k0 + a_col);
        As[a_col + 0][a_row] = av.x;
        As[a_col + 1][a_row] = av.y;
        As[a_col + 2][a_row] = av.z;
        As[a_col + 3][a_row] = av.w;

        float4 bv = *(const float4*)(B + (size_t)(k0 + b_row) * Ncols + block_col + b_col);
        *(float4*)&Bs[b_row][b_col] = bv;

        __syncthreads();

        #pragma unroll
        for (int k = 0; k < BK; k++) {
            float4 a0 = *(const float4*)&As[k][tm];
            float4 a1 = *(const float4*)&As[k][tm + 4];
            float4 b0 = *(const float4*)&Bs[k][tn];
            float4 b1 = *(const float4*)&Bs[k][tn + 4];
            float ra[8] = {a0.x, a0.y, a0.z, a0.w, a1.x, a1.y, a1.z, a1.w};
            float rb[8] = {b0.x, b0.y, b0.z, b0.w, b1.x, b1.y, b1.z, b1.w};
            #pragma unroll
            for (int i = 0; i < 8; i++)
                #pragma unroll
                for (int j = 0; j < 8; j++)
                    acc[i][j] = fmaf(ra[i], rb[j], acc[i][j]);
        }
        __syncthreads();
    }

    // epilogue
    float bvreg[8];
    #pragma unroll
    for (int j = 0; j < 8; j++)
        bvreg[j] = bias ? bias[block_col + tn + j] : 0.0f;

    #pragma unroll
    for (int i = 0; i < 8; i++) {
        int gr = block_row + tm + i;
        if (gr < M) {
            float* crow = C + (size_t)gr * Ncols + block_col + tn;
            #pragma unroll
            for (int j = 0; j < 8; j += 4) {
                float4 v;
                v.x = acc[i][j + 0] + bvreg[j + 0];
                v.y = acc[i][j + 1] + bvreg[j + 1];
                v.z = acc[i][j + 2] + bvreg[j + 2];
                v.w = acc[i][j + 3] + bvreg[j + 3];
                if (relu) {
                    v.x = fmaxf(v.x, 0.f); v.y = fmaxf(v.y, 0.f);
                    v.z = fmaxf(v.z, 0.f); v.w = fmaxf(v.w, 0.f);
                }
                *(float4*)(crow + j) = v;
            }
        }
    }
}

// ---------------- acc init: acc[i,:] = bias + m[i,:] * dinv[i]^2 (self-loop fused) ----------------
__global__ void init_acc_kernel(const float* __restrict__ m, const float* __restrict__ dinv,
                                const float* __restrict__ bias, float* __restrict__ acc, int n)
{
    long long i = (long long)blockIdx.x * blockDim.x + threadIdx.x;  // float4 index
    long long total = (long long)n * (HDIM / 4);
    if (i >= total) return;
    int row = (int)(i >> 6);           // / 64
    int col4 = (int)(i & 63);
    float w = dinv[row]; w = w * w;
    float4 v = ((const float4*)m)[i];
    float4 b = ((const float4*)bias)[col4];
    float4 o;
    o.x = fmaf(v.x, w, b.x);
    o.y = fmaf(v.y, w, b.y);
    o.z = fmaf(v.z, w, b.z);
    o.w = fmaf(v.w, w, b.w);
    ((float4*)acc)[i] = o;
}

// ---------------- edge scatter: acc[dst,:] += m[src,:] * dinv[src]*dinv[dst] ----------------
// One warp per edge; each lane handles 8 floats (2x red.v4).
__global__ void scatter_kernel(const float* __restrict__ m, const int* __restrict__ src,
                               const int* __restrict__ dst, const float* __restrict__ dinv,
                               float* __restrict__ acc, int E)
{
    int gw = (blockIdx.x * blockDim.x + threadIdx.x) >> 5;
    int lane = threadIdx.x & 31;
    if (gw >= E) return;
    int s = src[gw], d = dst[gw];
    float w = dinv[s] * dinv[d];
    const float4* mrow = (const float4*)(m + (size_t)s * HDIM);
    float* arow = acc + (size_t)d * HDIM;
    #pragma unroll
    for (int it = 0; it < 2; it++) {
        int j = lane + it * 32;              // float4 index 0..63
        float4 v = mrow[j];
        v.x *= w; v.y *= w; v.z *= w; v.w *= w;
        unsigned long long gaddr = __cvta_generic_to_global(arow + j * 4);
        asm volatile("red.global.add.v4.f32 [%0], {%1, %2, %3, %4};"
                     :: "l"(gaddr), "f"(v.x), "f"(v.y), "f"(v.z), "f"(v.w)
                     : "memory");
    }
}

// ---------------- relu pass ----------------
__global__ void relu_kernel(const float* __restrict__ in, float* __restrict__ out, long long nv4)
{
    long long i = (long long)blockIdx.x * blockDim.x + threadIdx.x;
    if (i >= nv4) return;
    float4 v = ((const float4*)in)[i];
    float4 o;
    o.x = fmaxf(v.x, 0.f); o.y = fmaxf(v.y, 0.f);
    o.z = fmaxf(v.z, 0.f); o.w = fmaxf(v.w, 0.f);
    ((float4*)out)[i] = o;
}

extern "C" void kernel_launch(void* const* d_in, const int* in_sizes, int n_in,
                              void* d_out, int out_size)
{
    const float* x  = (const float*)d_in[0];
    const int*   ei = (const int*)d_in[1];
    const float* w1 = (const float*)d_in[2];
    const float* b1 = (const float*)d_in[3];
    const float* w2 = (const float*)d_in[4];
    const float* b2 = (const float*)d_in[5];
    const float* gw = (const float*)d_in[6];
    const float* gb = (const float*)d_in[7];

    int N = in_sizes[0] / FIN;
    int E = in_sizes[1] / 2;
    int L = in_sizes[6] / (HDIM * HDIM);
    const int* srcp = ei;
    const int* dstp = ei + E;

    float *h, *m, *acc, *dinv;
    cudaGetSymbolAddress((void**)&h,    g_h);
    cudaGetSymbolAddress((void**)&m,    g_m);
    cudaGetSymbolAddress((void**)&acc,  g_acc);
    cudaGetSymbolAddress((void**)&dinv, g_dinv);

    // degrees -> dinv
    init_deg_kernel<<<(N + 255) / 256, 256>>>(dinv, N);
    count_deg_kernel<<<(E + 255) / 256, 256>>>(dstp, dinv, E);
    dinv_kernel<<<(N + 255) / 256, 256>>>(dinv, N);

    dim3 gemm_grid((N + BM - 1) / BM, HDIM / BN);

    // encoder
    sgemm_kernel<<<gemm_grid, 256>>>(x, w1, b1, m, N, HDIM, FIN, 1);   // relu(x@w1+b1)
    sgemm_kernel<<<gemm_grid, 256>>>(m, w2, b2, h, N, HDIM, HDIM, 0);  // @w2+b2

    long long nv4 = (long long)N * (HDIM / 4);
    int ew_blocks = (int)((nv4 + 255) / 256);
    int sc_blocks = (int)(((long long)E * 32 + 255) / 256);

    for (int l = 0; l < L; l++) {
        sgemm_kernel<<<gemm_grid, 256>>>(h, gw + (size_t)l * HDIM * HDIM, nullptr, m, N, HDIM, HDIM, 0);
        init_acc_kernel<<<ew_blocks, 256>>>(m, dinv, gb + (size_t)l * HDIM, acc, N);
        scatter_kernel<<<sc_blocks, 256>>>(m, srcp, dstp, dinv, acc, E);
        float* dest = (l == L - 1) ? (float*)d_out : h;
        relu_kernel<<<ew_blocks, 256>>>(acc, dest, nv4);
    }
}

// round 7
// speedup vs baseline: 1.0718x; 1.0718x over previous
#include <cuda_runtime.h>
#include <cstdint>

#define NODES_MAX 100000
#define EDGES_MAX 300000
#define HDIM 256
#define FIN 128

// Scratch (allocation-free rule: __device__ globals)
__device__ __align__(16) float g_h[(size_t)NODES_MAX * HDIM];
__device__ __align__(16) float g_m[(size_t)NODES_MAX * HDIM];
__device__ float g_dinv[NODES_MAX];
__device__ int   g_deg[NODES_MAX];
__device__ int   g_off[NODES_MAX + 1];
__device__ int   g_cur[NODES_MAX];
__device__ int   g_esrc[EDGES_MAX];

// ---------------- degree / norm / CSR build ----------------
__global__ void init_deg_kernel(int* deg, int n) {
    int i = blockIdx.x * blockDim.x + threadIdx.x;
    if (i < n) deg[i] = 1;  // self-loop
}

__global__ void count_deg_kernel(const int* __restrict__ dst, int* deg, int E) {
    int i = blockIdx.x * blockDim.x + threadIdx.x;
    if (i < E) atomicAdd(&deg[dst[i]], 1);
}

__global__ void dinv_kernel(const int* __restrict__ deg, float* dinv, int n) {
    int i = blockIdx.x * blockDim.x + threadIdx.x;
    if (i < n) dinv[i] = rsqrtf((float)deg[i]);  // deg >= 1 always
}

// Single-block exclusive scan of (deg[i] - 1) = in-edge counts -> offsets into g_esrc.
// n <= 100000, 1024 threads, each handles a contiguous chunk.
__global__ void scan_kernel(const int* __restrict__ deg, int* __restrict__ off, int n) {
    __shared__ int ssum[1024];
    int t = threadIdx.x;
    int chunk = (n + 1023) / 1024;
    int start = t * chunk;
    int end = start + chunk; if (end > n) end = n;
    int s = 0;
    for (int i = start; i < end; i++) s += deg[i] - 1;  // edges only (no self-loop)
    ssum[t] = s;
    __syncthreads();
    // Hillis-Steele inclusive scan over 1024 partials
    for (int ofs = 1; ofs < 1024; ofs <<= 1) {
        int other = (t >= ofs) ? ssum[t - ofs] : 0;
        __syncthreads();
        ssum[t] += other;
        __syncthreads();
    }
    int base = (t == 0) ? 0 : ssum[t - 1];
    int run = base;
    for (int i = start; i < end; i++) {
        off[i] = run;
        run += deg[i] - 1;
    }
    if (t == 1023) off[n] = ssum[1023];
}

__global__ void cursor_copy_kernel(const int* __restrict__ off, int* cur, int n) {
    int i = blockIdx.x * blockDim.x + threadIdx.x;
    if (i < n) cur[i] = off[i];
}

__global__ void fill_kernel(const int* __restrict__ src, const int* __restrict__ dst,
                            int* cur, int* __restrict__ esrc, int E) {
    int i = blockIdx.x * blockDim.x + threadIdx.x;
    if (i < E) {
        int d = dst[i];
        int p = atomicAdd(&cur[d], 1);
        esrc[p] = src[i];
    }
}

// ---------------- SGEMM: C[M,Ncols] = A[M,K] @ B[K,Ncols] (+bias)(+relu) ----------------
#define BM 128
#define BN 128
#define BK 8

__global__ __launch_bounds__(256, 2)
void sgemm_kernel(const float* __restrict__ A, const float* __restrict__ B,
                  const float* __restrict__ bias, float* __restrict__ C,
                  int M, int Ncols, int K, int relu)
{
    __shared__ float As[BK][BM];
    __shared__ float Bs[BK][BN];

    int tid = threadIdx.x;
    int block_row = blockIdx.x * BM;
    int block_col = blockIdx.y * BN;

    int a_row = tid >> 1;
    int a_col = (tid & 1) * 4;
    int b_row = tid >> 5;
    int b_col = (tid & 31) * 4;

    int tm = (tid >> 4) * 8;
    int tn = (tid & 15) * 8;

    float acc[8][8];
    #pragma unroll
    for (int i = 0; i < 8; i++)
        #pragma unroll
        for (int j = 0; j < 8; j++) acc[i][j] = 0.0f;

    for (int k0 = 0; k0 < K; k0 += BK) {
        int gr = block_row + a_row;
        float4 av = make_float4(0.f, 0.f, 0.f, 0.f);
        if (gr < M) av = *(const float4*)(A + (size_t)gr * K + k0 + a_col);
        As[a_col + 0][a_row] = av.x;
        As[a_col + 1][a_row] = av.y;
        As[a_col + 2][a_row] = av.z;
        As[a_col + 3][a_row] = av.w;

        float4 bv = *(const float4*)(B + (size_t)(k0 + b_row) * Ncols + block_col + b_col);
        *(float4*)&Bs[b_row][b_col] = bv;

        __syncthreads();

        #pragma unroll
        for (int k = 0; k < BK; k++) {
            float4 a0 = *(const float4*)&As[k][tm];
            float4 a1 = *(const float4*)&As[k][tm + 4];
            float4 b0 = *(const float4*)&Bs[k][tn];
            float4 b1 = *(const float4*)&Bs[k][tn + 4];
            float ra[8] = {a0.x, a0.y, a0.z, a0.w, a1.x, a1.y, a1.z, a1.w};
            float rb[8] = {b0.x, b0.y, b0.z, b0.w, b1.x, b1.y, b1.z, b1.w};
            #pragma unroll
            for (int i = 0; i < 8; i++)
                #pragma unroll
                for (int j = 0; j < 8; j++)
                    acc[i][j] = fmaf(ra[i], rb[j], acc[i][j]);
        }
        __syncthreads();
    }

    float bvreg[8];
    #pragma unroll
    for (int j = 0; j < 8; j++)
        bvreg[j] = bias ? bias[block_col + tn + j] : 0.0f;

    #pragma unroll
    for (int i = 0; i < 8; i++) {
        int gr = block_row + tm + i;
        if (gr < M) {
            float* crow = C + (size_t)gr * Ncols + block_col + tn;
            #pragma unroll
            for (int j = 0; j < 8; j += 4) {
                float4 v;
                v.x = acc[i][j + 0] + bvreg[j + 0];
                v.y = acc[i][j + 1] + bvreg[j + 1];
                v.z = acc[i][j + 2] + bvreg[j + 2];
                v.w = acc[i][j + 3] + bvreg[j + 3];
                if (relu) {
                    v.x = fmaxf(v.x, 0.f); v.y = fmaxf(v.y, 0.f);
                    v.z = fmaxf(v.z, 0.f); v.w = fmaxf(v.w, 0.f);
                }
                *(float4*)(crow + j) = v;
            }
        }
    }
}

// ---------------- fused aggregate: out[i] = relu(bias + dinv[i]^2*m[i] + sum_e dinv[s]*dinv[i]*m[s]) ----------------
// One warp per node, register accumulation, zero atomics, ReLU + bias fused.
__global__ __launch_bounds__(256)
void aggregate_kernel(const float* __restrict__ m, const int* __restrict__ off,
                      const int* __restrict__ esrc, const float* __restrict__ dinv,
                      const float* __restrict__ bias, float* __restrict__ out, int n)
{
    int node = (blockIdx.x * blockDim.x + threadIdx.x) >> 5;
    int lane = threadIdx.x & 31;
    if (node >= n) return;

    float di = __ldg(&dinv[node]);
    const float4* bias4 = (const float4*)bias;
    const float4* mrow = (const float4*)(m + (size_t)node * HDIM);

    float4 a0 = bias4[lane];
    float4 a1 = bias4[lane + 32];

    // self-loop
    float ws = di * di;
    float4 v0 = mrow[lane];
    float4 v1 = mrow[lane + 32];
    a0.x = fmaf(ws, v0.x, a0.x); a0.y = fmaf(ws, v0.y, a0.y);
    a0.z = fmaf(ws, v0.z, a0.z); a0.w = fmaf(ws, v0.w, a0.w);
    a1.x = fmaf(ws, v1.x, a1.x); a1.y = fmaf(ws, v1.y, a1.y);
    a1.z = fmaf(ws, v1.z, a1.z); a1.w = fmaf(ws, v1.w, a1.w);

    int e = __ldg(&off[node]);
    int e1 = __ldg(&off[node + 1]);

    if (e < e1) {
        int s = __ldg(&esrc[e]);
        float wd = __ldg(&dinv[s]);
        while (true) {
            const float4* sr = (const float4*)(m + (size_t)s * HDIM);
            float4 u0 = sr[lane];
            float4 u1 = sr[lane + 32];
            // prefetch next edge while this row's loads are in flight
            int sn = 0; float wdn = 0.f;
            if (e + 1 < e1) { sn = __ldg(&esrc[e + 1]); wdn = __ldg(&dinv[sn]); }
            float w = wd * di;
            a0.x = fmaf(w, u0.x, a0.x); a0.y = fmaf(w, u0.y, a0.y);
            a0.z = fmaf(w, u0.z, a0.z); a0.w = fmaf(w, u0.w, a0.w);
            a1.x = fmaf(w, u1.x, a1.x); a1.y = fmaf(w, u1.y, a1.y);
            a1.z = fmaf(w, u1.z, a1.z); a1.w = fmaf(w, u1.w, a1.w);
            e++;
            if (e >= e1) break;
            s = sn; wd = wdn;
        }
    }

    // ReLU + write
    a0.x = fmaxf(a0.x, 0.f); a0.y = fmaxf(a0.y, 0.f);
    a0.z = fmaxf(a0.z, 0.f); a0.w = fmaxf(a0.w, 0.f);
    a1.x = fmaxf(a1.x, 0.f); a1.y = fmaxf(a1.y, 0.f);
    a1.z = fmaxf(a1.z, 0.f); a1.w = fmaxf(a1.w, 0.f);

    float4* orow = (float4*)(out + (size_t)node * HDIM);
    orow[lane] = a0;
    orow[lane + 32] = a1;
}

extern "C" void kernel_launch(void* const* d_in, const int* in_sizes, int n_in,
                              void* d_out, int out_size)
{
    const float* x  = (const float*)d_in[0];
    const int*   ei = (const int*)d_in[1];
    const float* w1 = (const float*)d_in[2];
    const float* b1 = (const float*)d_in[3];
    const float* w2 = (const float*)d_in[4];
    const float* b2 = (const float*)d_in[5];
    const float* gw = (const float*)d_in[6];
    const float* gb = (const float*)d_in[7];

    int N = in_sizes[0] / FIN;
    int E = in_sizes[1] / 2;
    int L = in_sizes[6] / (HDIM * HDIM);
    const int* srcp = ei;
    const int* dstp = ei + E;

    float *h, *m, *dinv;
    int *deg, *off, *cur, *esrc;
    cudaGetSymbolAddress((void**)&h,    g_h);
    cudaGetSymbolAddress((void**)&m,    g_m);
    cudaGetSymbolAddress((void**)&dinv, g_dinv);
    cudaGetSymbolAddress((void**)&deg,  g_deg);
    cudaGetSymbolAddress((void**)&off,  g_off);
    cudaGetSymbolAddress((void**)&cur,  g_cur);
    cudaGetSymbolAddress((void**)&esrc, g_esrc);

    int nb = (N + 255) / 256;
    int eb = (E + 255) / 256;

    // degrees -> dinv, CSR build
    init_deg_kernel<<<nb, 256>>>(deg, N);
    count_deg_kernel<<<eb, 256>>>(dstp, deg, E);
    dinv_kernel<<<nb, 256>>>(deg, dinv, N);
    scan_kernel<<<1, 1024>>>(deg, off, N);
    cursor_copy_kernel<<<nb, 256>>>(off, cur, N);
    fill_kernel<<<eb, 256>>>(srcp, dstp, cur, esrc, E);

    dim3 gemm_grid((N + BM - 1) / BM, HDIM / BN);

    // encoder
    sgemm_kernel<<<gemm_grid, 256>>>(x, w1, b1, m, N, HDIM, FIN, 1);   // relu(x@w1+b1)
    sgemm_kernel<<<gemm_grid, 256>>>(m, w2, b2, h, N, HDIM, HDIM, 0);  // @w2+b2

    int agg_blocks = (int)(((long long)N * 32 + 255) / 256);

    for (int l = 0; l < L; l++) {
        sgemm_kernel<<<gemm_grid, 256>>>(h, gw + (size_t)l * HDIM * HDIM, nullptr, m, N, HDIM, HDIM, 0);
        float* dest = (l == L - 1) ? (float*)d_out : h;
        aggregate_kernel<<<agg_blocks, 256>>>(m, off, esrc, dinv, gb + (size_t)l * HDIM, dest, N);
    }
}

// round 9
// speedup vs baseline: 1.5662x; 1.4614x over previous
#include <cuda_runtime.h>
#include <cuda_bf16.h>
#include <mma.h>
#include <cstdint>

using namespace nvcuda;

#define NODES_MAX 100000
#define EDGES_MAX 300000
#define HDIM 256
#define FIN 128

// ---------------- scratch (allocation-free rule: __device__ globals) ----------------
__device__ __align__(16) float g_h[(size_t)NODES_MAX * HDIM];
__device__ __align__(16) float g_m[(size_t)NODES_MAX * HDIM];
__device__ float g_dinv[NODES_MAX];
__device__ int   g_deg[NODES_MAX];
__device__ int   g_off[NODES_MAX + 1];
__device__ int   g_cur[NODES_MAX];
__device__ int   g_esrc[EDGES_MAX];
__device__ int   g_bsum[512];
__device__ int   g_bpre[512];
// split-bf16 weights, original [K,256] layout: 5 slots (K<=256)
__device__ __align__(16) __nv_bfloat16 g_wh[5 * 256 * 256];
__device__ __align__(16) __nv_bfloat16 g_wl[5 * 256 * 256];

// ---------------- degree / norm / CSR build ----------------
__global__ void init_deg_kernel(int* deg, int n) {
    int i = blockIdx.x * blockDim.x + threadIdx.x;
    if (i < n) deg[i] = 1;
}
__global__ void count_deg_kernel(const int* __restrict__ dst, int* deg, int E) {
    int i = blockIdx.x * blockDim.x + threadIdx.x;
    if (i < E) atomicAdd(&deg[dst[i]], 1);
}
__global__ void dinv_kernel(const int* __restrict__ deg, float* dinv, int n) {
    int i = blockIdx.x * blockDim.x + threadIdx.x;
    if (i < n) dinv[i] = rsqrtf((float)deg[i]);
}
// parallel scan, 3 stages
__global__ void bsum_kernel(const int* __restrict__ deg, int* bsum, int n) {
    __shared__ int sh[256];
    int i = blockIdx.x * 256 + threadIdx.x;
    sh[threadIdx.x] = (i < n) ? deg[i] - 1 : 0;
    __syncthreads();
    for (int o = 128; o > 0; o >>= 1) {
        if (threadIdx.x < o) sh[threadIdx.x] += sh[threadIdx.x + o];
        __syncthreads();
    }
    if (threadIdx.x == 0) bsum[blockIdx.x] = sh[0];
}
__global__ void bscan_kernel(const int* __restrict__ bsum, int* bpre, int nb, int* off, int n) {
    __shared__ int sh[512];
    int t = threadIdx.x;
    int v = (t < nb) ? bsum[t] : 0;
    sh[t] = v; __syncthreads();
    for (int o = 1; o < 512; o <<= 1) {
        int u = (t >= o) ? sh[t - o] : 0;
        __syncthreads();
        sh[t] += u;
        __syncthreads();
    }
    if (t < nb) bpre[t] = sh[t] - v;           // exclusive
    if (t == 511) off[n] = sh[511];            // total edge count
}
__global__ void off_kernel(const int* __restrict__ deg, const int* __restrict__ bpre,
                           int* __restrict__ off, int n) {
    __shared__ int sh[256];
    int i = blockIdx.x * 256 + threadIdx.x;
    int v = (i < n) ? deg[i] - 1 : 0;
    sh[threadIdx.x] = v; __syncthreads();
    for (int o = 1; o < 256; o <<= 1) {
        int u = (threadIdx.x >= o) ? sh[threadIdx.x - o] : 0;
        __syncthreads();
        sh[threadIdx.x] += u;
        __syncthreads();
    }
    if (i < n) off[i] = bpre[blockIdx.x] + sh[threadIdx.x] - v;
}
__global__ void cursor_copy_kernel(const int* __restrict__ off, int* cur, int n) {
    int i = blockIdx.x * blockDim.x + threadIdx.x;
    if (i < n) cur[i] = off[i];
}
__global__ void fill_kernel(const int* __restrict__ src, const int* __restrict__ dst,
                            int* cur, int* __restrict__ esrc, int E) {
    int i = blockIdx.x * blockDim.x + threadIdx.x;
    if (i < E) {
        int d = dst[i];
        int p = atomicAdd(&cur[d], 1);
        esrc[p] = src[i];
    }
}

// ---------------- weight prep: W[K,256] fp32 -> hi/lo bf16, same layout ----------------
__global__ void wprep_kernel(const float* __restrict__ W, __nv_bfloat16* __restrict__ Wh,
                             __nv_bfloat16* __restrict__ Wl, int total) {
    int idx = blockIdx.x * 256 + threadIdx.x;
    if (idx >= total) return;
    float f = W[idx];
    __nv_bfloat16 hb = __float2bfloat16_rn(f);
    Wh[idx] = hb;
    Wl[idx] = __float2bfloat16_rn(f - __bfloat162float(hb));
}

// ---------------- wmma split-bf16 GEMM: C[M,256] = A[M,K] @ W (+bias)(+relu) ----------------
// CTA tile 128x128 (grid.y = 2 for N=256), BK=32, 8 warps each 64x32 (4x2 wmma frags).
// smem layout (bytes): sAh@0 (128*40*2=10240), sAl@10240, sBh@20480 (32*136*2=8704),
// sBl@29184 (end 37888); epilogue stage fp32 128*128*4=65536 reuses from 0. Total 65536.
#define PADA 40
#define PADB 136
#define OFF_AL 10240
#define OFF_BH 20480
#define OFF_BL 29184
#define WSMEM 65536

__global__ __launch_bounds__(256)
void wgemm_kernel(const float* __restrict__ A, const __nv_bfloat16* __restrict__ Bh,
                  const __nv_bfloat16* __restrict__ Bl, const float* __restrict__ bias,
                  float* __restrict__ C, int M, int K, int relu)
{
    extern __shared__ char smem[];
    __nv_bfloat16* sAh = (__nv_bfloat16*)(smem);
    __nv_bfloat16* sAl = (__nv_bfloat16*)(smem + OFF_AL);
    __nv_bfloat16* sBh = (__nv_bfloat16*)(smem + OFF_BH);
    __nv_bfloat16* sBl = (__nv_bfloat16*)(smem + OFF_BL);
    float* stage = (float*)smem;

    int tid = threadIdx.x;
    int wid = tid >> 5;
    int wm = wid >> 2;        // 0..1 -> 64-row slab
    int wn = wid & 3;         // 0..3 -> 32-col slab
    int row0 = blockIdx.x * 128;
    int col0 = blockIdx.y * 128;

    wmma::fragment<wmma::accumulator, 16, 16, 16, float> acc[4][2];
    #pragma unroll
    for (int i = 0; i < 4; i++)
        #pragma unroll
        for (int j = 0; j < 2; j++) wmma::fill_fragment(acc[i][j], 0.0f);

    for (int k0 = 0; k0 < K; k0 += 32) {
        // ---- A tile: 128 rows x 32 cols fp32 -> split hi/lo bf16 ----
        #pragma unroll
        for (int it = 0; it < 4; it++) {
            int idx = it * 256 + tid;       // 0..1023
            int r = idx >> 3;               // 0..127
            int c4 = (idx & 7) * 4;         // 0..28
            int grow = row0 + r;
            float4 f = (grow < M) ? *(const float4*)(A + (size_t)grow * K + k0 + c4)
                                  : make_float4(0.f, 0.f, 0.f, 0.f);
            uint32_t h01, h23, l01, l23;
            asm("cvt.rn.bf16x2.f32 %0, %1, %2;" : "=r"(h01) : "f"(f.y), "f"(f.x));
            asm("cvt.rn.bf16x2.f32 %0, %1, %2;" : "=r"(h23) : "f"(f.w), "f"(f.z));
            float r0 = f.x - __uint_as_float(h01 << 16);
            float r1 = f.y - __uint_as_float(h01 & 0xFFFF0000u);
            float r2 = f.z - __uint_as_float(h23 << 16);
            float r3 = f.w - __uint_as_float(h23 & 0xFFFF0000u);
            asm("cvt.rn.bf16x2.f32 %0, %1, %2;" : "=r"(l01) : "f"(r1), "f"(r0));
            asm("cvt.rn.bf16x2.f32 %0, %1, %2;" : "=r"(l23) : "f"(r3), "f"(r2));
            *(uint2*)(sAh + r * PADA + c4) = make_uint2(h01, h23);
            *(uint2*)(sAl + r * PADA + c4) = make_uint2(l01, l23);
        }
        // ---- B tile: 32 rows x 128 cols bf16 (pre-split) ----
        #pragma unroll
        for (int it = 0; it < 2; it++) {
            int idx = it * 256 + tid;       // 0..511
            int r = idx >> 4;               // 0..31
            int c8 = (idx & 15) * 8;        // 0..120
            size_t go = (size_t)(k0 + r) * 256 + col0 + c8;
            *(uint4*)(sBh + r * PADB + c8) = *(const uint4*)(Bh + go);
            *(uint4*)(sBl + r * PADB + c8) = *(const uint4*)(Bl + go);
        }
        __syncthreads();

        #pragma unroll
        for (int ks = 0; ks < 2; ks++) {
            wmma::fragment<wmma::matrix_a, 16, 16, 16, __nv_bfloat16, wmma::row_major> ah[4], al[4];
            wmma::fragment<wmma::matrix_b, 16, 16, 16, __nv_bfloat16, wmma::row_major> bh[2], bl[2];
            #pragma unroll
            for (int i = 0; i < 4; i++) {
                wmma::load_matrix_sync(ah[i], sAh + (wm * 64 + i * 16) * PADA + ks * 16, PADA);
                wmma::load_matrix_sync(al[i], sAl + (wm * 64 + i * 16) * PADA + ks * 16, PADA);
            }
            #pragma unroll
            for (int j = 0; j < 2; j++) {
                wmma::load_matrix_sync(bh[j], sBh + (ks * 16) * PADB + wn * 32 + j * 16, PADB);
                wmma::load_matrix_sync(bl[j], sBl + (ks * 16) * PADB + wn * 32 + j * 16, PADB);
            }
            #pragma unroll
            for (int i = 0; i < 4; i++)
                #pragma unroll
                for (int j = 0; j < 2; j++) {
                    wmma::mma_sync(acc[i][j], ah[i], bh[j], acc[i][j]);
                    wmma::mma_sync(acc[i][j], ah[i], bl[j], acc[i][j]);
                    wmma::mma_sync(acc[i][j], al[i], bh[j], acc[i][j]);
                }
        }
        __syncthreads();
    }

    // ---- epilogue: stage -> bias/relu -> coalesced store ----
    #pragma unroll
    for (int i = 0; i < 4; i++)
        #pragma unroll
        for (int j = 0; j < 2; j++)
            wmma::store_matrix_sync(stage + (wm * 64 + i * 16) * 128 + wn * 32 + j * 16,
                                    acc[i][j], 128, wmma::mem_row_major);
    __syncthreads();

    #pragma unroll
    for (int it = 0; it < 16; it++) {
        int idx = it * 256 + tid;           // 0..4095
        int r = idx >> 5;                   // 0..127
        int c4 = (idx & 31) * 4;            // 0..124
        int grow = row0 + r;
        if (grow < M) {
            float4 v = *(float4*)(stage + r * 128 + c4);
            if (bias) {
                v.x += bias[col0 + c4 + 0]; v.y += bias[col0 + c4 + 1];
                v.z += bias[col0 + c4 + 2]; v.w += bias[col0 + c4 + 3];
            }
            if (relu) {
                v.x = fmaxf(v.x, 0.f); v.y = fmaxf(v.y, 0.f);
                v.z = fmaxf(v.z, 0.f); v.w = fmaxf(v.w, 0.f);
            }
            *(float4*)(C + (size_t)grow * 256 + col0 + c4) = v;
        }
    }
}

// ---------------- fused aggregate (unchanged) ----------------
__global__ __launch_bounds__(256)
void aggregate_kernel(const float* __restrict__ m, const int* __restrict__ off,
                      const int* __restrict__ esrc, const float* __restrict__ dinv,
                      const float* __restrict__ bias, float* __restrict__ out, int n)
{
    int node = (blockIdx.x * blockDim.x + threadIdx.x) >> 5;
    int lane = threadIdx.x & 31;
    if (node >= n) return;

    float di = __ldg(&dinv[node]);
    const float4* bias4 = (const float4*)bias;
    const float4* mrow = (const float4*)(m + (size_t)node * HDIM);

    float4 a0 = bias4[lane];
    float4 a1 = bias4[lane + 32];

    float ws = di * di;
    float4 v0 = mrow[lane];
    float4 v1 = mrow[lane + 32];
    a0.x = fmaf(ws, v0.x, a0.x); a0.y = fmaf(ws, v0.y, a0.y);
    a0.z = fmaf(ws, v0.z, a0.z); a0.w = fmaf(ws, v0.w, a0.w);
    a1.x = fmaf(ws, v1.x, a1.x); a1.y = fmaf(ws, v1.y, a1.y);
    a1.z = fmaf(ws, v1.z, a1.z); a1.w = fmaf(ws, v1.w, a1.w);

    int e = __ldg(&off[node]);
    int e1 = __ldg(&off[node + 1]);

    if (e < e1) {
        int s = __ldg(&esrc[e]);
        float wd = __ldg(&dinv[s]);
        while (true) {
            const float4* sr = (const float4*)(m + (size_t)s * HDIM);
            float4 u0 = sr[lane];
            float4 u1 = sr[lane + 32];
            int sn = 0; float wdn = 0.f;
            if (e + 1 < e1) { sn = __ldg(&esrc[e + 1]); wdn = __ldg(&dinv[sn]); }
            float w = wd * di;
            a0.x = fmaf(w, u0.x, a0.x); a0.y = fmaf(w, u0.y, a0.y);
            a0.z = fmaf(w, u0.z, a0.z); a0.w = fmaf(w, u0.w, a0.w);
            a1.x = fmaf(w, u1.x, a1.x); a1.y = fmaf(w, u1.y, a1.y);
            a1.z = fmaf(w, u1.z, a1.z); a1.w = fmaf(w, u1.w, a1.w);
            e++;
            if (e >= e1) break;
            s = sn; wd = wdn;
        }
    }

    a0.x = fmaxf(a0.x, 0.f); a0.y = fmaxf(a0.y, 0.f);
    a0.z = fmaxf(a0.z, 0.f); a0.w = fmaxf(a0.w, 0.f);
    a1.x = fmaxf(a1.x, 0.f); a1.y = fmaxf(a1.y, 0.f);
    a1.z = fmaxf(a1.z, 0.f); a1.w = fmaxf(a1.w, 0.f);

    float4* orow = (float4*)(out + (size_t)node * HDIM);
    orow[lane] = a0;
    orow[lane + 32] = a1;
}

extern "C" void kernel_launch(void* const* d_in, const int* in_sizes, int n_in,
                              void* d_out, int out_size)
{
    const float* x  = (const float*)d_in[0];
    const int*   ei = (const int*)d_in[1];
    const float* w1 = (const float*)d_in[2];
    const float* b1 = (const float*)d_in[3];
    const float* w2 = (const float*)d_in[4];
    const float* b2 = (const float*)d_in[5];
    const float* gw = (const float*)d_in[6];
    const float* gb = (const float*)d_in[7];

    int N = in_sizes[0] / FIN;
    int E = in_sizes[1] / 2;
    int L = in_sizes[6] / (HDIM * HDIM);
    const int* srcp = ei;
    const int* dstp = ei + E;

    float *h, *m, *dinv;
    int *deg, *off, *cur, *esrc, *bsum, *bpre;
    __nv_bfloat16 *wh, *wl;
    cudaGetSymbolAddress((void**)&h,    g_h);
    cudaGetSymbolAddress((void**)&m,    g_m);
    cudaGetSymbolAddress((void**)&dinv, g_dinv);
    cudaGetSymbolAddress((void**)&deg,  g_deg);
    cudaGetSymbolAddress((void**)&off,  g_off);
    cudaGetSymbolAddress((void**)&cur,  g_cur);
    cudaGetSymbolAddress((void**)&esrc, g_esrc);
    cudaGetSymbolAddress((void**)&bsum, g_bsum);
    cudaGetSymbolAddress((void**)&bpre, g_bpre);
    cudaGetSymbolAddress((void**)&wh,   g_wh);
    cudaGetSymbolAddress((void**)&wl,   g_wl);

    cudaFuncSetAttribute(wgemm_kernel, cudaFuncAttributeMaxDynamicSharedMemorySize, WSMEM);

    int nb = (N + 255) / 256;   // 391
    int eb = (E + 255) / 256;

    // degrees -> dinv; parallel scan; CSR fill
    init_deg_kernel<<<nb, 256>>>(deg, N);
    count_deg_kernel<<<eb, 256>>>(dstp, deg, E);
    dinv_kernel<<<nb, 256>>>(deg, dinv, N);
    bsum_kernel<<<nb, 256>>>(deg, bsum, N);
    bscan_kernel<<<1, 512>>>(bsum, bpre, nb, off, N);
    off_kernel<<<nb, 256>>>(deg, bpre, off, N);
    cursor_copy_kernel<<<nb, 256>>>(off, cur, N);
    fill_kernel<<<eb, 256>>>(srcp, dstp, cur, esrc, E);

    // weight prep: slot 0 = enc_w1 (K=128), 1 = enc_w2, 2.. = gcn layers
    const size_t WS = 256 * 256;
    wprep_kernel<<<(FIN * 256 + 255) / 256, 256>>>(w1, wh, wl, FIN * 256);
    wprep_kernel<<<(HDIM * 256 + 255) / 256, 256>>>(w2, wh + WS, wl + WS, HDIM * 256);
    for (int l = 0; l < L; l++)
        wprep_kernel<<<(HDIM * 256 + 255) / 256, 256>>>(gw + (size_t)l * HDIM * HDIM,
                                                        wh + WS * (2 + l), wl + WS * (2 + l),
                                                        HDIM * 256);

    dim3 gemm_grid((N + 127) / 128, 2);

    // encoder
    wgemm_kernel<<<gemm_grid, 256, WSMEM>>>(x, wh, wl, b1, m, N, FIN, 1);
    wgemm_kernel<<<gemm_grid, 256, WSMEM>>>(m, wh + WS, wl + WS, b2, h, N, HDIM, 0);

    int agg_blocks = (int)(((long long)N * 32 + 255) / 256);

    for (int l = 0; l < L; l++) {
        wgemm_kernel<<<gemm_grid, 256, WSMEM>>>(h, wh + WS * (2 + l), wl + WS * (2 + l),
                                                nullptr, m, N, HDIM, 0);
        float* dest = (l == L - 1) ? (float*)d_out : h;
        aggregate_kernel<<<agg_blocks, 256>>>(m, off, esrc, dinv, gb + (size_t)l * HDIM, dest, N);
    }
}